// round 2
// baseline (speedup 1.0000x reference)
#include <cuda_runtime.h>
#include <math.h>

// Problem constants (fixed by the dataset)
#define BB 1024
#define SS 64
#define DD 512
#define RR 16
#define CC 1000

// Scratch: __device__ globals (no runtime allocation allowed)
__device__ float g_lrc[(size_t)BB * DD * RR];   // 33.5 MB: low_rank_cov flat [B, D*R]
__device__ float g_std[(size_t)BB * DD];        //  2.1 MB: diagonal_std   [B, D]
__device__ float g_pre[(size_t)BB * SS * DD];   //  134 MB: pre_logits     [B*S, D]

// ---------------------------------------------------------------------------
// Generic C = A(MxK) * B^T(NxK) + bias, row-major, K % 16 == 0.
// 128x128 tile, 16-deep k-slab, 256 threads, 8x8 per-thread micro-tile.
// EPI: 0 = plain, 1 = softplus(x)+1e-3, 2 = x * (1/1.5)
// ---------------------------------------------------------------------------
template <int EPI>
__global__ __launch_bounds__(256) void gemm_tn(
    const float* __restrict__ A, const float* __restrict__ Bm,
    const float* __restrict__ bias, float* __restrict__ Cm,
    int M, int N, int K)
{
    __shared__ float As[16][128];
    __shared__ float Bs[16][128];

    const int bm  = blockIdx.y * 128;
    const int bn  = blockIdx.x * 128;
    const int tid = threadIdx.x;
    const int tx  = tid & 15;   // n-direction
    const int ty  = tid >> 4;   // m-direction

    // Loader mapping: each thread loads 8 contiguous floats (2x float4) of a
    // 128(row) x 16(k) slab: row = tid/2, col = (tid&1)*8.
    const int lrow = tid >> 1;
    const int lcol = (tid & 1) << 3;

    float acc[8][8];
#pragma unroll
    for (int i = 0; i < 8; i++)
#pragma unroll
        for (int j = 0; j < 8; j++) acc[i][j] = 0.f;

    for (int k0 = 0; k0 < K; k0 += 16) {
        // --- load A slab ---
        {
            const int gm = bm + lrow;
            float4 v0 = make_float4(0.f, 0.f, 0.f, 0.f), v1 = v0;
            if (gm < M) {
                const float* p = A + (size_t)gm * K + k0 + lcol;
                v0 = *(const float4*)(p);
                v1 = *(const float4*)(p + 4);
            }
            As[lcol + 0][lrow] = v0.x; As[lcol + 1][lrow] = v0.y;
            As[lcol + 2][lrow] = v0.z; As[lcol + 3][lrow] = v0.w;
            As[lcol + 4][lrow] = v1.x; As[lcol + 5][lrow] = v1.y;
            As[lcol + 6][lrow] = v1.z; As[lcol + 7][lrow] = v1.w;
        }
        // --- load B slab ---
        {
            const int gn = bn + lrow;
            float4 v0 = make_float4(0.f, 0.f, 0.f, 0.f), v1 = v0;
            if (gn < N) {
                const float* p = Bm + (size_t)gn * K + k0 + lcol;
                v0 = *(const float4*)(p);
                v1 = *(const float4*)(p + 4);
            }
            Bs[lcol + 0][lrow] = v0.x; Bs[lcol + 1][lrow] = v0.y;
            Bs[lcol + 2][lrow] = v0.z; Bs[lcol + 3][lrow] = v0.w;
            Bs[lcol + 4][lrow] = v1.x; Bs[lcol + 5][lrow] = v1.y;
            Bs[lcol + 6][lrow] = v1.z; Bs[lcol + 7][lrow] = v1.w;
        }
        __syncthreads();

#pragma unroll
        for (int kk = 0; kk < 16; kk++) {
            float4 a0 = *(const float4*)&As[kk][ty * 4];
            float4 a1 = *(const float4*)&As[kk][ty * 4 + 64];
            float4 b0 = *(const float4*)&Bs[kk][tx * 4];
            float4 b1 = *(const float4*)&Bs[kk][tx * 4 + 64];
            float ar[8] = {a0.x, a0.y, a0.z, a0.w, a1.x, a1.y, a1.z, a1.w};
            float br[8] = {b0.x, b0.y, b0.z, b0.w, b1.x, b1.y, b1.z, b1.w};
#pragma unroll
            for (int i = 0; i < 8; i++)
#pragma unroll
                for (int j = 0; j < 8; j++)
                    acc[i][j] = fmaf(ar[i], br[j], acc[i][j]);
        }
        __syncthreads();
    }

    // Epilogue: add bias, transform, store (elementwise, guarded)
#pragma unroll
    for (int i = 0; i < 8; i++) {
        const int gm = bm + ty * 4 + (i & 3) + ((i >> 2) << 6);
        if (gm >= M) continue;
#pragma unroll
        for (int j = 0; j < 8; j++) {
            const int gn = bn + tx * 4 + (j & 3) + ((j >> 2) << 6);
            if (gn >= N) continue;
            float v = acc[i][j] + bias[gn];
            if (EPI == 1) {
                // numerically stable softplus matching jax.nn.softplus
                v = fmaxf(v, 0.f) + log1pf(expf(-fabsf(v))) + 1e-3f;
            } else if (EPI == 2) {
                v *= (1.0f / 1.5f);
            }
            Cm[(size_t)gm * N + gn] = v;
        }
    }
}

// ---------------------------------------------------------------------------
// pre[b,s,d] = features[b,d] + std[b,d]*nd[b,s,d] + sum_r lrc[b,d,r]*nlr[b,s,r]
// One block per batch b; lrc row cached in smem (padded stride 17 => conflict-free).
// ---------------------------------------------------------------------------
__global__ __launch_bounds__(256) void prelogits_kernel(
    const float* __restrict__ features,
    const float* __restrict__ lrc,    // [B, D*R]
    const float* __restrict__ stdv,   // [B, D]
    const float* __restrict__ nd,     // [B, S, D]
    const float* __restrict__ nlr,    // [B, S, R]
    float* __restrict__ pre)          // [B*S, D]
{
    __shared__ float s_lrc[DD * 17];  // [d][r] padded: 34816 B
    __shared__ float s_f[DD];
    __shared__ float s_std[DD];

    const int b   = blockIdx.x;
    const int tid = threadIdx.x;

    const float* lb = lrc + (size_t)b * DD * RR;
    for (int i = tid; i < DD * RR; i += 256)
        s_lrc[(i >> 4) * 17 + (i & 15)] = lb[i];
    for (int i = tid; i < DD; i += 256) {
        s_f[i]   = features[(size_t)b * DD + i];
        s_std[i] = stdv[(size_t)b * DD + i];
    }
    __syncthreads();

    for (int s = 0; s < SS; s++) {
        const size_t row = (size_t)b * SS + s;
        const float* nlrp = nlr + row * RR;
        float nr[RR];
#pragma unroll
        for (int r = 0; r < RR; r++) nr[r] = nlrp[r];  // warp-broadcast loads

        const float* ndp = nd + row * DD;
        float* pp = pre + row * DD;
#pragma unroll
        for (int dd = 0; dd < DD / 256; dd++) {
            const int d = tid + dd * 256;
            float a = fmaf(s_std[d], ndp[d], s_f[d]);
            const float* lp = &s_lrc[d * 17];
#pragma unroll
            for (int r = 0; r < RR; r++) a = fmaf(lp[r], nr[r], a);
            pp[d] = a;
        }
    }
}

// ---------------------------------------------------------------------------
extern "C" void kernel_launch(void* const* d_in, const int* in_sizes, int n_in,
                              void* d_out, int out_size)
{
    const float* features   = (const float*)d_in[0];
    const float* W_cov      = (const float*)d_in[1];
    const float* b_cov      = (const float*)d_in[2];
    const float* W_diag     = (const float*)d_in[3];
    const float* b_diag     = (const float*)d_in[4];
    const float* W_cls      = (const float*)d_in[5];
    const float* b_cls      = (const float*)d_in[6];
    const float* noise_diag = (const float*)d_in[7];
    const float* noise_lr   = (const float*)d_in[8];
    float* out = (float*)d_out;

    float *lrc, *stdv, *pre;
    cudaGetSymbolAddress((void**)&lrc,  g_lrc);
    cudaGetSymbolAddress((void**)&stdv, g_std);
    cudaGetSymbolAddress((void**)&pre,  g_pre);

    dim3 blk(256);

    // G1: lrc_flat[B, D*R] = features @ W_cov^T + b_cov
    gemm_tn<0><<<dim3((DD * RR) / 128, BB / 128), blk>>>(
        features, W_cov, b_cov, lrc, BB, DD * RR, DD);

    // G2: std[B, D] = softplus(features @ W_diag^T + b_diag) + 1e-3
    gemm_tn<1><<<dim3(DD / 128, BB / 128), blk>>>(
        features, W_diag, b_diag, stdv, BB, DD, DD);

    // Fused elementwise: pre_logits
    prelogits_kernel<<<BB, blk>>>(features, lrc, stdv, noise_diag, noise_lr, pre);

    // G3: logits[B*S, C] = (pre @ W_cls^T + b_cls) / 1.5
    gemm_tn<2><<<dim3((CC + 127) / 128, (BB * SS) / 128), blk>>>(
        pre, W_cls, b_cls, out, BB * SS, CC, DD);
}

// round 4
// speedup vs baseline: 1.6388x; 1.6388x over previous
#include <cuda_runtime.h>
#include <math.h>
#include <stdint.h>

// Problem constants
#define BB 1024
#define SS 64
#define DD 512
#define RR 16
#define CC 1000

// ---------------------------------------------------------------------------
// Scratch (__device__ globals; float4 for 16B alignment needed by cp.async)
// ---------------------------------------------------------------------------
__device__ float4 g_lrc4 [(size_t)BB * DD * RR / 4];   // low_rank_cov [B, D*R]
__device__ float4 g_std4 [(size_t)BB * DD / 4];        // diagonal_std [B, D]
__device__ float4 g_pre4 [(size_t)BB * SS * DD / 4];   // pre_logits [B*S, D] (tf32-rounded)
__device__ float4 g_wcov4[(size_t)DD * RR * DD / 4];   // tf32-rounded W_cov
__device__ float4 g_wcls4[(size_t)CC * DD / 4];        // tf32-rounded W_cls
__device__ float4 g_feat4[(size_t)BB * DD / 4];        // tf32-rounded features

// ---------------------------------------------------------------------------
// Helpers
// ---------------------------------------------------------------------------
__device__ __forceinline__ uint32_t smem_u32(const void* p) {
    uint32_t a;
    asm("{ .reg .u64 t; cvta.to.shared.u64 t, %1; cvt.u32.u64 %0, t; }"
        : "=r"(a) : "l"(p));
    return a;
}
__device__ __forceinline__ float rtf32(float x) {  // round-to-nearest tf32
    uint32_t o; asm("cvt.rna.tf32.f32 %0, %1;" : "=r"(o) : "f"(x));
    return __uint_as_float(o);
}
__device__ __forceinline__ void cpa16(uint32_t dst, const void* src, uint32_t sz) {
    asm volatile("cp.async.cg.shared.global [%0], [%1], 16, %2;"
                 :: "r"(dst), "l"(src), "r"(sz) : "memory");
}
// m16n8k8 tf32 MMA (legacy HMMA path; legal on base sm_103 target)
__device__ __forceinline__ void mma8(float* d, const uint32_t* a, const uint32_t* b) {
    asm volatile(
        "mma.sync.aligned.m16n8k8.row.col.f32.tf32.tf32.f32 "
        "{%0,%1,%2,%3}, {%4,%5,%6,%7}, {%8,%9}, {%0,%1,%2,%3};"
        : "+f"(d[0]), "+f"(d[1]), "+f"(d[2]), "+f"(d[3])
        : "r"(a[0]), "r"(a[1]), "r"(a[2]), "r"(a[3]), "r"(b[0]), "r"(b[1]));
}

// ---------------------------------------------------------------------------
// tf32 tensor-core GEMM: C[M,N] = A[M,K] @ B[N,K]^T + bias (EPI==2: * 2/3)
// 128x128 tile, K-slab 32, 4-stage cp.async, 8 warps (4m x 2n), warp 32x64.
// Requires M%128==0, K%32==0, A/B rows 16B-aligned, inputs tf32-pre-rounded.
// ---------------------------------------------------------------------------
#define KSLAB 32
#define STGS  4
#define PAD   36                              // floats per smem row (conflict-free, 16B-mult)
#define STAGE_FLOATS (2 * 128 * PAD)          // A half + B half = 9216 floats
#define BOFF  (128 * PAD)
#define MMA_SMEM (STGS * STAGE_FLOATS * 4 + 512)

template <int EPI>
__global__ __launch_bounds__(256, 1) void mma_gemm(
    const float* __restrict__ A, const float* __restrict__ Bm,
    const float* __restrict__ bias, float* __restrict__ Cm,
    int M, int N, int K)
{
    extern __shared__ float sm[];
    float* s_bias = sm + STGS * STAGE_FLOATS;

    const int tid = threadIdx.x;
    const int bm  = blockIdx.y * 128;
    const int bn  = blockIdx.x * 128;

    if (tid < 128) s_bias[tid] = (bn + tid < N) ? bias[bn + tid] : 0.f;

    const int wid  = tid >> 5, lane = tid & 31;
    const int wm   = (wid & 3) * 32;     // warp m offset in tile
    const int wn   = (wid >> 2) * 64;    // warp n offset in tile
    const int g    = lane >> 2;          // group id (0..7)
    const int t    = lane & 3;           // thread-in-group (0..3)

    const uint32_t smb = smem_u32(sm);

    auto load_slab = [&](int s, int slab) {
        const int k0 = slab * KSLAB;
        const uint32_t abase = smb + (uint32_t)(s * STAGE_FLOATS) * 4u;
        const uint32_t bbase = abase + BOFF * 4u;
#pragma unroll
        for (int q = 0; q < 4; q++) {            // A: 128 rows x 8 k-chunks
            int idx = tid + q * 256;
            int m = idx >> 3, kc = idx & 7;
            cpa16(abase + (uint32_t)(m * PAD + kc * 4) * 4u,
                  A + (size_t)(bm + m) * K + k0 + kc * 4, 16);
        }
#pragma unroll
        for (int q = 0; q < 4; q++) {            // B: 128 rows x 8 k-chunks (N-guard)
            int idx = tid + q * 256;
            int n = idx >> 3, kc = idx & 7;
            int gn = bn + n;
            uint32_t sz = (gn < N) ? 16u : 0u;
            int gc = (gn < N) ? gn : (N - 1);
            cpa16(bbase + (uint32_t)(n * PAD + kc * 4) * 4u,
                  Bm + (size_t)gc * K + k0 + kc * 4, sz);
        }
    };

    float acc[2][8][4];
#pragma unroll
    for (int i = 0; i < 2; i++)
#pragma unroll
        for (int j = 0; j < 8; j++)
#pragma unroll
            for (int c = 0; c < 4; c++) acc[i][j][c] = 0.f;

    const int nslab = K / KSLAB;
    for (int p = 0; p < 3; p++) {
        load_slab(p, p);
        asm volatile("cp.async.commit_group;" ::: "memory");
    }

    for (int j = 0; j < nslab; j++) {
        if (j + 3 < nslab) load_slab((j + 3) & (STGS - 1), j + 3);
        asm volatile("cp.async.commit_group;" ::: "memory");
        asm volatile("cp.async.wait_group 3;" ::: "memory");
        __syncthreads();

        const uint32_t* Au = (const uint32_t*)(sm + (j & (STGS - 1)) * STAGE_FLOATS);
        const uint32_t* Bu = Au + BOFF;

#pragma unroll
        for (int ks = 0; ks < 4; ks++) {
            const int k0 = ks * 8;
            uint32_t af[2][4], bf[8][2];
#pragma unroll
            for (int mt = 0; mt < 2; mt++) {
                int r = wm + mt * 16 + g;
                af[mt][0] = Au[r * PAD + k0 + t];
                af[mt][1] = Au[(r + 8) * PAD + k0 + t];
                af[mt][2] = Au[r * PAD + k0 + t + 4];
                af[mt][3] = Au[(r + 8) * PAD + k0 + t + 4];
            }
#pragma unroll
            for (int nt = 0; nt < 8; nt++) {
                int n = wn + nt * 8 + g;
                bf[nt][0] = Bu[n * PAD + k0 + t];
                bf[nt][1] = Bu[n * PAD + k0 + t + 4];
            }
#pragma unroll
            for (int mt = 0; mt < 2; mt++)
#pragma unroll
                for (int nt = 0; nt < 8; nt++)
                    mma8(acc[mt][nt], af[mt], bf[nt]);
        }
        __syncthreads();
    }

    // Epilogue: bias (+ scale), vectorized float2 stores
#pragma unroll
    for (int mt = 0; mt < 2; mt++) {
        const int r0 = bm + wm + mt * 16 + g;
#pragma unroll
        for (int nt = 0; nt < 8; nt++) {
            const int lc = wn + nt * 8 + 2 * t;   // block-local col (even)
            const int gc = bn + lc;
            float b0 = s_bias[lc], b1 = s_bias[lc + 1];
            float v00 = acc[mt][nt][0] + b0, v01 = acc[mt][nt][1] + b1;
            float v10 = acc[mt][nt][2] + b0, v11 = acc[mt][nt][3] + b1;
            if (EPI == 2) {
                v00 *= (2.0f / 3.0f); v01 *= (2.0f / 3.0f);
                v10 *= (2.0f / 3.0f); v11 *= (2.0f / 3.0f);
            }
            if (gc + 1 < N) {
                *(float2*)(Cm + (size_t)r0 * N + gc)       = make_float2(v00, v01);
                *(float2*)(Cm + (size_t)(r0 + 8) * N + gc) = make_float2(v10, v11);
            } else if (gc < N) {
                Cm[(size_t)r0 * N + gc]       = v00;
                Cm[(size_t)(r0 + 8) * N + gc] = v10;
            }
        }
    }
}

// ---------------------------------------------------------------------------
// tf32 RN rounding pass
// ---------------------------------------------------------------------------
__global__ void round_tf32_k(const float4* __restrict__ in, float4* __restrict__ out, int n4) {
    int i = blockIdx.x * blockDim.x + threadIdx.x;
    if (i < n4) {
        float4 v = in[i];
        v.x = rtf32(v.x); v.y = rtf32(v.y); v.z = rtf32(v.z); v.w = rtf32(v.w);
        out[i] = v;
    }
}

// ---------------------------------------------------------------------------
// SIMT GEMM for G2 (softplus epilogue); small problem, fp32-exact
// ---------------------------------------------------------------------------
__global__ __launch_bounds__(256) void gemm_softplus(
    const float* __restrict__ A, const float* __restrict__ Bm,
    const float* __restrict__ bias, float* __restrict__ Cm,
    int M, int N, int K)
{
    __shared__ float As[16][128];
    __shared__ float Bs[16][128];
    const int bm = blockIdx.y * 128, bn = blockIdx.x * 128;
    const int tid = threadIdx.x, tx = tid & 15, ty = tid >> 4;
    const int lrow = tid >> 1, lcol = (tid & 1) << 3;

    float acc[8][8];
#pragma unroll
    for (int i = 0; i < 8; i++)
#pragma unroll
        for (int j = 0; j < 8; j++) acc[i][j] = 0.f;

    for (int k0 = 0; k0 < K; k0 += 16) {
        {
            const float* p = A + (size_t)(bm + lrow) * K + k0 + lcol;
            float4 v0 = *(const float4*)p, v1 = *(const float4*)(p + 4);
            As[lcol+0][lrow]=v0.x; As[lcol+1][lrow]=v0.y; As[lcol+2][lrow]=v0.z; As[lcol+3][lrow]=v0.w;
            As[lcol+4][lrow]=v1.x; As[lcol+5][lrow]=v1.y; As[lcol+6][lrow]=v1.z; As[lcol+7][lrow]=v1.w;
        }
        {
            const float* p = Bm + (size_t)(bn + lrow) * K + k0 + lcol;
            float4 v0 = *(const float4*)p, v1 = *(const float4*)(p + 4);
            Bs[lcol+0][lrow]=v0.x; Bs[lcol+1][lrow]=v0.y; Bs[lcol+2][lrow]=v0.z; Bs[lcol+3][lrow]=v0.w;
            Bs[lcol+4][lrow]=v1.x; Bs[lcol+5][lrow]=v1.y; Bs[lcol+6][lrow]=v1.z; Bs[lcol+7][lrow]=v1.w;
        }
        __syncthreads();
#pragma unroll
        for (int kk = 0; kk < 16; kk++) {
            float4 a0 = *(const float4*)&As[kk][ty*4];
            float4 a1 = *(const float4*)&As[kk][ty*4+64];
            float4 b0 = *(const float4*)&Bs[kk][tx*4];
            float4 b1 = *(const float4*)&Bs[kk][tx*4+64];
            float ar[8] = {a0.x,a0.y,a0.z,a0.w,a1.x,a1.y,a1.z,a1.w};
            float br[8] = {b0.x,b0.y,b0.z,b0.w,b1.x,b1.y,b1.z,b1.w};
#pragma unroll
            for (int i = 0; i < 8; i++)
#pragma unroll
                for (int j = 0; j < 8; j++) acc[i][j] = fmaf(ar[i], br[j], acc[i][j]);
        }
        __syncthreads();
    }
#pragma unroll
    for (int i = 0; i < 8; i++) {
        const int gm = bm + ty*4 + (i & 3) + ((i >> 2) << 6);
#pragma unroll
        for (int j = 0; j < 8; j++) {
            const int gn = bn + tx*4 + (j & 3) + ((j >> 2) << 6);
            float vv = acc[i][j] + bias[gn];
            vv = fmaxf(vv, 0.f) + log1pf(expf(-fabsf(vv))) + 1e-3f;
            Cm[(size_t)gm * N + gn] = vv;
        }
    }
}

// ---------------------------------------------------------------------------
// pre[b,s,d] = f + std*nd + sum_r lrc*nlr   (stores tf32-rounded)
// ---------------------------------------------------------------------------
__global__ __launch_bounds__(256) void prelogits_kernel(
    const float* __restrict__ features, const float* __restrict__ lrc,
    const float* __restrict__ stdv, const float* __restrict__ nd,
    const float* __restrict__ nlr, float* __restrict__ pre)
{
    __shared__ float s_lrc[DD * 17];
    __shared__ float s_f[DD];
    __shared__ float s_std[DD];
    const int b = blockIdx.x, tid = threadIdx.x;

    const float* lb = lrc + (size_t)b * DD * RR;
    for (int i = tid; i < DD * RR; i += 256)
        s_lrc[(i >> 4) * 17 + (i & 15)] = lb[i];
    for (int i = tid; i < DD; i += 256) {
        s_f[i]   = features[(size_t)b * DD + i];
        s_std[i] = stdv[(size_t)b * DD + i];
    }
    __syncthreads();

    for (int s = 0; s < SS; s++) {
        const size_t row = (size_t)b * SS + s;
        const float* nlrp = nlr + row * RR;
        float nr[RR];
#pragma unroll
        for (int r = 0; r < RR; r++) nr[r] = nlrp[r];
        const float* ndp = nd + row * DD;
        float* pp = pre + row * DD;
#pragma unroll
        for (int dd = 0; dd < DD / 256; dd++) {
            const int d = tid + dd * 256;
            float a = fmaf(s_std[d], ndp[d], s_f[d]);
            const float* lp = &s_lrc[d * 17];
#pragma unroll
            for (int r = 0; r < RR; r++) a = fmaf(lp[r], nr[r], a);
            pp[d] = rtf32(a);
        }
    }
}

// ---------------------------------------------------------------------------
extern "C" void kernel_launch(void* const* d_in, const int* in_sizes, int n_in,
                              void* d_out, int out_size)
{
    const float* features   = (const float*)d_in[0];
    const float* W_cov      = (const float*)d_in[1];
    const float* b_cov      = (const float*)d_in[2];
    const float* W_diag     = (const float*)d_in[3];
    const float* b_diag     = (const float*)d_in[4];
    const float* W_cls      = (const float*)d_in[5];
    const float* b_cls      = (const float*)d_in[6];
    const float* noise_diag = (const float*)d_in[7];
    const float* noise_lr   = (const float*)d_in[8];
    float* out = (float*)d_out;

    float4 *lrc4, *std4, *pre4, *wcov4, *wcls4, *feat4;
    cudaGetSymbolAddress((void**)&lrc4,  g_lrc4);
    cudaGetSymbolAddress((void**)&std4,  g_std4);
    cudaGetSymbolAddress((void**)&pre4,  g_pre4);
    cudaGetSymbolAddress((void**)&wcov4, g_wcov4);
    cudaGetSymbolAddress((void**)&wcls4, g_wcls4);
    cudaGetSymbolAddress((void**)&feat4, g_feat4);
    float* lrc  = (float*)lrc4;
    float* stdv = (float*)std4;
    float* pre  = (float*)pre4;

    cudaFuncSetAttribute(mma_gemm<0>, cudaFuncAttributeMaxDynamicSharedMemorySize, MMA_SMEM);
    cudaFuncSetAttribute(mma_gemm<2>, cudaFuncAttributeMaxDynamicSharedMemorySize, MMA_SMEM);

    // Pre-round tf32 inputs (RN)
    const int n4_feat = BB * DD / 4;
    const int n4_wcov = DD * RR * DD / 4;
    const int n4_wcls = CC * DD / 4;
    round_tf32_k<<<(n4_feat + 255) / 256, 256>>>((const float4*)features, feat4, n4_feat);
    round_tf32_k<<<(n4_wcov + 255) / 256, 256>>>((const float4*)W_cov,    wcov4, n4_wcov);
    round_tf32_k<<<(n4_wcls + 255) / 256, 256>>>((const float4*)W_cls,    wcls4, n4_wcls);

    // G1: lrc[B, D*R] = feat @ W_cov^T + b_cov   (tf32 tensor cores)
    mma_gemm<0><<<dim3((DD * RR) / 128, BB / 128), 256, MMA_SMEM>>>(
        (const float*)feat4, (const float*)wcov4, b_cov, lrc, BB, DD * RR, DD);

    // G2: std = softplus(feat @ W_diag^T) + 1e-3   (SIMT fp32)
    gemm_softplus<<<dim3(DD / 128, BB / 128), 256>>>(
        features, W_diag, b_diag, stdv, BB, DD, DD);

    // pre_logits (fused elementwise, tf32-rounded)
    prelogits_kernel<<<BB, 256>>>(features, lrc, stdv, noise_diag, noise_lr, pre);

    // G3: out = (pre @ W_cls^T + b_cls) / 1.5   (tf32 tensor cores)
    mma_gemm<2><<<dim3((CC + 127) / 128, (BB * SS) / 128), 256, MMA_SMEM>>>(
        pre, (const float*)wcls4, b_cls, out, BB * SS, CC, DD);
}

// round 5
// speedup vs baseline: 3.0711x; 1.8739x over previous
#include <cuda_runtime.h>
#include <math.h>
#include <stdint.h>

// Problem constants
#define BB 1024
#define SS 64
#define DD 512
#define RR 16
#define CC 1000

// ---------------------------------------------------------------------------
// Scratch (__device__ globals; float4 for 16B alignment needed by cp.async)
// ---------------------------------------------------------------------------
__device__ float4 g_lrc4  [(size_t)BB * DD * RR / 4];  // low_rank_cov [B, D*R]
__device__ float4 g_std4  [(size_t)BB * DD / 4];       // diagonal_std [B, D]
__device__ float4 g_pre4  [(size_t)BB * SS * DD / 4];  // pre_logits [B*S, D] (tf32-rounded)
__device__ float4 g_wcov4 [(size_t)DD * RR * DD / 4];  // tf32-rounded W_cov
__device__ float4 g_wcls4 [(size_t)CC * DD / 4];       // tf32-rounded W_cls
__device__ float4 g_wdiag4[(size_t)DD * DD / 4];       // tf32-rounded W_diag
__device__ float4 g_feat4 [(size_t)BB * DD / 4];       // tf32-rounded features

// ---------------------------------------------------------------------------
// Helpers
// ---------------------------------------------------------------------------
__device__ __forceinline__ uint32_t smem_u32(const void* p) {
    uint32_t a;
    asm("{ .reg .u64 t; cvta.to.shared.u64 t, %1; cvt.u32.u64 %0, t; }"
        : "=r"(a) : "l"(p));
    return a;
}
__device__ __forceinline__ float rtf32(float x) {  // round-to-nearest tf32
    uint32_t o; asm("cvt.rna.tf32.f32 %0, %1;" : "=r"(o) : "f"(x));
    return __uint_as_float(o);
}
__device__ __forceinline__ void cpa16(uint32_t dst, const void* src, uint32_t sz) {
    asm volatile("cp.async.cg.shared.global [%0], [%1], 16, %2;"
                 :: "r"(dst), "l"(src), "r"(sz) : "memory");
}
// m16n8k8 tf32 MMA (legacy HMMA path; legal on base sm_103 target)
__device__ __forceinline__ void mma8(float* d, const uint32_t* a, const uint32_t* b) {
    asm volatile(
        "mma.sync.aligned.m16n8k8.row.col.f32.tf32.tf32.f32 "
        "{%0,%1,%2,%3}, {%4,%5,%6,%7}, {%8,%9}, {%0,%1,%2,%3};"
        : "+f"(d[0]), "+f"(d[1]), "+f"(d[2]), "+f"(d[3])
        : "r"(a[0]), "r"(a[1]), "r"(a[2]), "r"(a[3]), "r"(b[0]), "r"(b[1]));
}

// ---------------------------------------------------------------------------
// tf32 tensor-core GEMM: C[M,N] = A[M,K] @ B[N,K]^T + bias
// EPI: 0 plain, 1 softplus(x)+1e-3, 2 x*(2/3)
// 128x128 tile, K-slab 32, 3-stage cp.async (2 ahead), ONE barrier per slab,
// 8 warps (4m x 2n), warp 32x64, 2 CTAs/SM.
// Requires M%128==0, K%32==0, inputs tf32-pre-rounded, rows 16B-aligned.
// ---------------------------------------------------------------------------
#define KSLAB 32
#define STGS  3
#define AHEAD 2
#define PAD   36                              // floats per smem row (conflict-free, 16B-mult)
#define STAGE_FLOATS (2 * 128 * PAD)          // A half + B half = 9216 floats
#define BOFF  (128 * PAD)
#define MMA_SMEM (STGS * STAGE_FLOATS * 4 + 512)   // 111104 B -> 2 CTAs/SM

template <int EPI>
__global__ __launch_bounds__(256, 2) void mma_gemm(
    const float* __restrict__ A, const float* __restrict__ Bm,
    const float* __restrict__ bias, float* __restrict__ Cm,
    int M, int N, int K)
{
    extern __shared__ float sm[];
    float* s_bias = sm + STGS * STAGE_FLOATS;

    const int tid = threadIdx.x;
    const int bm  = blockIdx.y * 128;
    const int bn  = blockIdx.x * 128;

    if (tid < 128) s_bias[tid] = (bn + tid < N) ? bias[bn + tid] : 0.f;

    const int wid  = tid >> 5, lane = tid & 31;
    const int wm   = (wid & 3) * 32;     // warp m offset
    const int wn   = (wid >> 2) * 64;    // warp n offset
    const int g    = lane >> 2;          // group (0..7)
    const int t    = lane & 3;           // thread-in-group (0..3)

    const uint32_t smb = smem_u32(sm);

    auto load_slab = [&](int s, int slab) {
        const int k0 = slab * KSLAB;
        const uint32_t abase = smb + (uint32_t)(s * STAGE_FLOATS) * 4u;
        const uint32_t bbase = abase + BOFF * 4u;
#pragma unroll
        for (int q = 0; q < 4; q++) {            // A: 128 rows x 8 k-chunks
            int idx = tid + q * 256;
            int m = idx >> 3, kc = idx & 7;
            cpa16(abase + (uint32_t)(m * PAD + kc * 4) * 4u,
                  A + (size_t)(bm + m) * K + k0 + kc * 4, 16);
        }
#pragma unroll
        for (int q = 0; q < 4; q++) {            // B: 128 rows x 8 k-chunks (N-guard)
            int idx = tid + q * 256;
            int n = idx >> 3, kc = idx & 7;
            int gn = bn + n;
            uint32_t sz = (gn < N) ? 16u : 0u;
            int gc = (gn < N) ? gn : (N - 1);
            cpa16(bbase + (uint32_t)(n * PAD + kc * 4) * 4u,
                  Bm + (size_t)gc * K + k0 + kc * 4, sz);
        }
    };

    float acc[2][8][4];
#pragma unroll
    for (int i = 0; i < 2; i++)
#pragma unroll
        for (int j = 0; j < 8; j++)
#pragma unroll
            for (int c = 0; c < 4; c++) acc[i][j][c] = 0.f;

    const int nslab = K / KSLAB;
    for (int p = 0; p < AHEAD; p++) {
        load_slab(p, p);
        asm volatile("cp.async.commit_group;" ::: "memory");
    }

    for (int j = 0; j < nslab; j++) {
        asm volatile("cp.async.wait_group 1;" ::: "memory");   // slab j resident
        __syncthreads();   // everyone past iter j-1 compute; slab j visible
        if (j + AHEAD < nslab) load_slab((j + AHEAD) % STGS, j + AHEAD);
        asm volatile("cp.async.commit_group;" ::: "memory");

        const uint32_t* Au = (const uint32_t*)(sm + (j % STGS) * STAGE_FLOATS);
        const uint32_t* Bu = Au + BOFF;

#pragma unroll
        for (int ks = 0; ks < 4; ks++) {
            const int k0 = ks * 8;
            uint32_t af[2][4], bf[8][2];
#pragma unroll
            for (int mt = 0; mt < 2; mt++) {
                int r = wm + mt * 16 + g;
                af[mt][0] = Au[r * PAD + k0 + t];
                af[mt][1] = Au[(r + 8) * PAD + k0 + t];
                af[mt][2] = Au[r * PAD + k0 + t + 4];
                af[mt][3] = Au[(r + 8) * PAD + k0 + t + 4];
            }
#pragma unroll
            for (int nt = 0; nt < 8; nt++) {
                int n = wn + nt * 8 + g;
                bf[nt][0] = Bu[n * PAD + k0 + t];
                bf[nt][1] = Bu[n * PAD + k0 + t + 4];
            }
#pragma unroll
            for (int mt = 0; mt < 2; mt++)
#pragma unroll
                for (int nt = 0; nt < 8; nt++)
                    mma8(acc[mt][nt], af[mt], bf[nt]);
        }
    }

    // Epilogue: bias + transform, float2 stores
#pragma unroll
    for (int mt = 0; mt < 2; mt++) {
        const int r0 = bm + wm + mt * 16 + g;
#pragma unroll
        for (int nt = 0; nt < 8; nt++) {
            const int lc = wn + nt * 8 + 2 * t;
            const int gc = bn + lc;
            float b0 = s_bias[lc], b1 = s_bias[lc + 1];
            float v00 = acc[mt][nt][0] + b0, v01 = acc[mt][nt][1] + b1;
            float v10 = acc[mt][nt][2] + b0, v11 = acc[mt][nt][3] + b1;
            if (EPI == 1) {
                v00 = fmaxf(v00, 0.f) + log1pf(expf(-fabsf(v00))) + 1e-3f;
                v01 = fmaxf(v01, 0.f) + log1pf(expf(-fabsf(v01))) + 1e-3f;
                v10 = fmaxf(v10, 0.f) + log1pf(expf(-fabsf(v10))) + 1e-3f;
                v11 = fmaxf(v11, 0.f) + log1pf(expf(-fabsf(v11))) + 1e-3f;
            } else if (EPI == 2) {
                v00 *= (2.0f / 3.0f); v01 *= (2.0f / 3.0f);
                v10 *= (2.0f / 3.0f); v11 *= (2.0f / 3.0f);
            }
            if (gc + 1 < N) {
                *(float2*)(Cm + (size_t)r0 * N + gc)       = make_float2(v00, v01);
                *(float2*)(Cm + (size_t)(r0 + 8) * N + gc) = make_float2(v10, v11);
            } else if (gc < N) {
                Cm[(size_t)r0 * N + gc]       = v00;
                Cm[(size_t)(r0 + 8) * N + gc] = v10;
            }
        }
    }
}

// ---------------------------------------------------------------------------
// tf32 RN rounding pass
// ---------------------------------------------------------------------------
__global__ void round_tf32_k(const float4* __restrict__ in, float4* __restrict__ out, int n4) {
    int i = blockIdx.x * blockDim.x + threadIdx.x;
    if (i < n4) {
        float4 v = in[i];
        v.x = rtf32(v.x); v.y = rtf32(v.y); v.z = rtf32(v.z); v.w = rtf32(v.w);
        out[i] = v;
    }
}

// ---------------------------------------------------------------------------
// pre[b,s,d] = f + std*nd + sum_r lrc*nlr   (stores tf32-rounded)
// ---------------------------------------------------------------------------
__global__ __launch_bounds__(256) void prelogits_kernel(
    const float* __restrict__ features, const float* __restrict__ lrc,
    const float* __restrict__ stdv, const float* __restrict__ nd,
    const float* __restrict__ nlr, float* __restrict__ pre)
{
    __shared__ float s_lrc[DD * 17];
    __shared__ float s_f[DD];
    __shared__ float s_std[DD];
    const int b = blockIdx.x, tid = threadIdx.x;

    const float* lb = lrc + (size_t)b * DD * RR;
    for (int i = tid; i < DD * RR; i += 256)
        s_lrc[(i >> 4) * 17 + (i & 15)] = lb[i];
    for (int i = tid; i < DD; i += 256) {
        s_f[i]   = features[(size_t)b * DD + i];
        s_std[i] = stdv[(size_t)b * DD + i];
    }
    __syncthreads();

    for (int s = 0; s < SS; s++) {
        const size_t row = (size_t)b * SS + s;
        const float* nlrp = nlr + row * RR;
        float nr[RR];
#pragma unroll
        for (int r = 0; r < RR; r++) nr[r] = nlrp[r];
        const float* ndp = nd + row * DD;
        float* pp = pre + row * DD;
#pragma unroll
        for (int dd = 0; dd < DD / 256; dd++) {
            const int d = tid + dd * 256;
            float a = fmaf(s_std[d], ndp[d], s_f[d]);
            const float* lp = &s_lrc[d * 17];
#pragma unroll
            for (int r = 0; r < RR; r++) a = fmaf(lp[r], nr[r], a);
            pp[d] = rtf32(a);
        }
    }
}

// ---------------------------------------------------------------------------
extern "C" void kernel_launch(void* const* d_in, const int* in_sizes, int n_in,
                              void* d_out, int out_size)
{
    const float* features   = (const float*)d_in[0];
    const float* W_cov      = (const float*)d_in[1];
    const float* b_cov      = (const float*)d_in[2];
    const float* W_diag     = (const float*)d_in[3];
    const float* b_diag     = (const float*)d_in[4];
    const float* W_cls      = (const float*)d_in[5];
    const float* b_cls      = (const float*)d_in[6];
    const float* noise_diag = (const float*)d_in[7];
    const float* noise_lr   = (const float*)d_in[8];
    float* out = (float*)d_out;

    float4 *lrc4, *std4, *pre4, *wcov4, *wcls4, *wdiag4, *feat4;
    cudaGetSymbolAddress((void**)&lrc4,   g_lrc4);
    cudaGetSymbolAddress((void**)&std4,   g_std4);
    cudaGetSymbolAddress((void**)&pre4,   g_pre4);
    cudaGetSymbolAddress((void**)&wcov4,  g_wcov4);
    cudaGetSymbolAddress((void**)&wcls4,  g_wcls4);
    cudaGetSymbolAddress((void**)&wdiag4, g_wdiag4);
    cudaGetSymbolAddress((void**)&feat4,  g_feat4);
    float* lrc  = (float*)lrc4;
    float* stdv = (float*)std4;
    float* pre  = (float*)pre4;

    cudaFuncSetAttribute(mma_gemm<0>, cudaFuncAttributeMaxDynamicSharedMemorySize, MMA_SMEM);
    cudaFuncSetAttribute(mma_gemm<1>, cudaFuncAttributeMaxDynamicSharedMemorySize, MMA_SMEM);
    cudaFuncSetAttribute(mma_gemm<2>, cudaFuncAttributeMaxDynamicSharedMemorySize, MMA_SMEM);

    // Pre-round tf32 inputs (RN)
    const int n4_feat  = BB * DD / 4;
    const int n4_wcov  = DD * RR * DD / 4;
    const int n4_wcls  = CC * DD / 4;
    const int n4_wdiag = DD * DD / 4;
    round_tf32_k<<<(n4_feat  + 255) / 256, 256>>>((const float4*)features, feat4,  n4_feat);
    round_tf32_k<<<(n4_wcov  + 255) / 256, 256>>>((const float4*)W_cov,    wcov4,  n4_wcov);
    round_tf32_k<<<(n4_wcls  + 255) / 256, 256>>>((const float4*)W_cls,    wcls4,  n4_wcls);
    round_tf32_k<<<(n4_wdiag + 255) / 256, 256>>>((const float4*)W_diag,   wdiag4, n4_wdiag);

    // G1: lrc[B, D*R] = feat @ W_cov^T + b_cov
    mma_gemm<0><<<dim3((DD * RR) / 128, BB / 128), 256, MMA_SMEM>>>(
        (const float*)feat4, (const float*)wcov4, b_cov, lrc, BB, DD * RR, DD);

    // G2: std = softplus(feat @ W_diag^T + b_diag) + 1e-3
    mma_gemm<1><<<dim3(DD / 128, BB / 128), 256, MMA_SMEM>>>(
        (const float*)feat4, (const float*)wdiag4, b_diag, stdv, BB, DD, DD);

    // pre_logits (fused elementwise, tf32-rounded)
    prelogits_kernel<<<BB, 256>>>(features, lrc, stdv, noise_diag, noise_lr, pre);

    // G3: out = (pre @ W_cls^T + b_cls) / 1.5
    mma_gemm<2><<<dim3((CC + 127) / 128, (BB * SS) / 128), 256, MMA_SMEM>>>(
        pre, (const float*)wcls4, b_cls, out, BB * SS, CC, DD);
}

// round 7
// speedup vs baseline: 3.3941x; 1.1052x over previous
#include <cuda_runtime.h>
#include <math.h>
#include <stdint.h>

// Problem constants
#define BB 1024
#define SS 64
#define DD 512
#define RR 16
#define CC 1000

// ---------------------------------------------------------------------------
// Scratch (__device__ globals; float4 for 16B alignment needed by cp.async)
// ---------------------------------------------------------------------------
__device__ float4 g_lrc4  [(size_t)BB * DD * RR / 4];  // low_rank_cov [B, D*R]
__device__ float4 g_std4  [(size_t)BB * DD / 4];       // diagonal_std [B, D]
__device__ float4 g_pre4  [(size_t)BB * SS * DD / 4];  // pre_logits [B*S, D] (tf32-rounded)
__device__ float4 g_wcov4 [(size_t)DD * RR * DD / 4];  // tf32-rounded W_cov
__device__ float4 g_wcls4 [(size_t)CC * DD / 4];       // tf32-rounded W_cls
__device__ float4 g_wdiag4[(size_t)DD * DD / 4];       // tf32-rounded W_diag
__device__ float4 g_feat4 [(size_t)BB * DD / 4];       // tf32-rounded features

// ---------------------------------------------------------------------------
// Helpers
// ---------------------------------------------------------------------------
__device__ __forceinline__ uint32_t smem_u32(const void* p) {
    uint32_t a;
    asm("{ .reg .u64 t; cvta.to.shared.u64 t, %1; cvt.u32.u64 %0, t; }"
        : "=r"(a) : "l"(p));
    return a;
}
__device__ __forceinline__ float rtf32(float x) {  // round-to-nearest tf32
    uint32_t o; asm("cvt.rna.tf32.f32 %0, %1;" : "=r"(o) : "f"(x));
    return __uint_as_float(o);
}
__device__ __forceinline__ void cpa16(uint32_t dst, const void* src, uint32_t sz) {
    asm volatile("cp.async.cg.shared.global [%0], [%1], 16, %2;"
                 :: "r"(dst), "l"(src), "r"(sz) : "memory");
}
// m16n8k8 tf32 MMA (legacy HMMA path; legal on base sm_103 target)
__device__ __forceinline__ void mma8(float* d, const uint32_t* a, const uint32_t* b) {
    asm volatile(
        "mma.sync.aligned.m16n8k8.row.col.f32.tf32.tf32.f32 "
        "{%0,%1,%2,%3}, {%4,%5,%6,%7}, {%8,%9}, {%0,%1,%2,%3};"
        : "+f"(d[0]), "+f"(d[1]), "+f"(d[2]), "+f"(d[3])
        : "r"(a[0]), "r"(a[1]), "r"(a[2]), "r"(a[3]), "r"(b[0]), "r"(b[1]));
}
// ldmatrix x4 (b16 view; one m8n8.b16 tile == one 8x4 tf32 fragment tile)
__device__ __forceinline__ void ldsm4(uint32_t* r, uint32_t addr) {
    asm volatile("ldmatrix.sync.aligned.m8n8.x4.shared.b16 {%0,%1,%2,%3}, [%4];"
        : "=r"(r[0]), "=r"(r[1]), "=r"(r[2]), "=r"(r[3]) : "r"(addr));
}

// ---------------------------------------------------------------------------
// tf32 tensor-core GEMM: C[M,N] = A[M,K] @ B[N,K]^T + bias
// EPI: 0 plain, 1 softplus(x)+1e-3, 2 x*(2/3)
// 128x128 tile, K-slab 32, 3-stage cp.async (2 ahead), ONE barrier per slab,
// 8 warps (4m x 2n), warp 32x64, 2 CTAs/SM, ldmatrix fragment loads.
// Requires M%128==0, K%32==0, inputs tf32-pre-rounded, rows 16B-aligned.
// ---------------------------------------------------------------------------
#define KSLAB 32
#define STGS  3
#define AHEAD 2
#define PAD   36                              // floats/smem row: ldmatrix conflict-free, 16B-mult
#define STAGE_FLOATS (2 * 128 * PAD)          // A half + B half = 9216 floats
#define BOFF  (128 * PAD)
#define MMA_SMEM (STGS * STAGE_FLOATS * 4 + 512)   // 111104 B -> 2 CTAs/SM

template <int EPI>
__global__ __launch_bounds__(256, 2) void mma_gemm(
    const float* __restrict__ A, const float* __restrict__ Bm,
    const float* __restrict__ bias, float* __restrict__ Cm,
    int M, int N, int K)
{
    extern __shared__ float sm[];
    float* s_bias = sm + STGS * STAGE_FLOATS;

    const int tid = threadIdx.x;
    const int bm  = blockIdx.y * 128;
    const int bn  = blockIdx.x * 128;

    if (tid < 128) s_bias[tid] = (bn + tid < N) ? bias[bn + tid] : 0.f;

    const int wid  = tid >> 5, lane = tid & 31;
    const int wm   = (wid & 3) * 32;     // warp m offset
    const int wn   = (wid >> 2) * 64;    // warp n offset
    const int g    = lane >> 2;          // group (0..7)
    const int t    = lane & 3;           // thread-in-group (0..3)

    const uint32_t smb = smem_u32(sm);

    // per-lane ldmatrix byte offsets within a stage (k0=0 base; +32B per k8 step)
    // A, mt: tiles {rows+0@k0, rows+8@k0, rows+0@k0+4, rows+8@k0+4}  (= a0..a3)
    // B, p : tiles {n+0@k0, n+0@k0+4, n+8@k0, n+8@k0+4}  (= b[2p][0],b[2p][1],b[2p+1][0],b[2p+1][1])
    const int tile = lane >> 3, rit = lane & 7;
    uint32_t aoff[2], boff[4];
#pragma unroll
    for (int mt = 0; mt < 2; mt++)
        aoff[mt] = (uint32_t)(((wm + mt * 16 + ((tile & 1) << 3) + rit) * PAD
                               + ((tile >> 1) << 2)) * 4);
#pragma unroll
    for (int p = 0; p < 4; p++)
        boff[p] = (uint32_t)((BOFF + (wn + p * 16 + ((tile >> 1) << 3) + rit) * PAD
                               + ((tile & 1) << 2)) * 4);

    auto load_slab = [&](int s, int slab) {
        const int k0 = slab * KSLAB;
        const uint32_t abase = smb + (uint32_t)(s * STAGE_FLOATS) * 4u;
        const uint32_t bbase = abase + BOFF * 4u;
#pragma unroll
        for (int q = 0; q < 4; q++) {            // A: 128 rows x 8 k-chunks
            int idx = tid + q * 256;
            int m = idx >> 3, kc = idx & 7;
            cpa16(abase + (uint32_t)(m * PAD + kc * 4) * 4u,
                  A + (size_t)(bm + m) * K + k0 + kc * 4, 16);
        }
#pragma unroll
        for (int q = 0; q < 4; q++) {            // B: 128 rows x 8 k-chunks (N-guard)
            int idx = tid + q * 256;
            int n = idx >> 3, kc = idx & 7;
            int gn = bn + n;
            uint32_t sz = (gn < N) ? 16u : 0u;
            int gc = (gn < N) ? gn : (N - 1);
            cpa16(bbase + (uint32_t)(n * PAD + kc * 4) * 4u,
                  Bm + (size_t)gc * K + k0 + kc * 4, sz);
        }
    };

    float acc[2][8][4];
#pragma unroll
    for (int i = 0; i < 2; i++)
#pragma unroll
        for (int j = 0; j < 8; j++)
#pragma unroll
            for (int c = 0; c < 4; c++) acc[i][j][c] = 0.f;

    const int nslab = K / KSLAB;
    for (int p = 0; p < AHEAD; p++) {
        load_slab(p, p);
        asm volatile("cp.async.commit_group;" ::: "memory");
    }

    for (int j = 0; j < nslab; j++) {
        asm volatile("cp.async.wait_group 1;" ::: "memory");   // slab j resident
        __syncthreads();   // everyone past iter j-1 compute; slab j visible
        if (j + AHEAD < nslab) load_slab((j + AHEAD) % STGS, j + AHEAD);
        asm volatile("cp.async.commit_group;" ::: "memory");

        const uint32_t stg = smb + (uint32_t)((j % STGS) * STAGE_FLOATS) * 4u;

#pragma unroll
        for (int ks = 0; ks < 4; ks++) {
            const uint32_t kb = stg + (uint32_t)ks * 32u;
            uint32_t af[2][4], bf[4][4];
            ldsm4(af[0], kb + aoff[0]);
            ldsm4(af[1], kb + aoff[1]);
#pragma unroll
            for (int p = 0; p < 4; p++) ldsm4(bf[p], kb + boff[p]);
#pragma unroll
            for (int mt = 0; mt < 2; mt++)
#pragma unroll
                for (int nt = 0; nt < 8; nt++)
                    mma8(acc[mt][nt], af[mt], &bf[nt >> 1][(nt & 1) << 1]);
        }
    }

    // Epilogue: bias + transform, float2 stores
#pragma unroll
    for (int mt = 0; mt < 2; mt++) {
        const int r0 = bm + wm + mt * 16 + g;
#pragma unroll
        for (int nt = 0; nt < 8; nt++) {
            const int lc = wn + nt * 8 + 2 * t;
            const int gc = bn + lc;
            float b0 = s_bias[lc], b1 = s_bias[lc + 1];
            float v00 = acc[mt][nt][0] + b0, v01 = acc[mt][nt][1] + b1;
            float v10 = acc[mt][nt][2] + b0, v11 = acc[mt][nt][3] + b1;
            if (EPI == 1) {
                v00 = fmaxf(v00, 0.f) + log1pf(expf(-fabsf(v00))) + 1e-3f;
                v01 = fmaxf(v01, 0.f) + log1pf(expf(-fabsf(v01))) + 1e-3f;
                v10 = fmaxf(v10, 0.f) + log1pf(expf(-fabsf(v10))) + 1e-3f;
                v11 = fmaxf(v11, 0.f) + log1pf(expf(-fabsf(v11))) + 1e-3f;
            } else if (EPI == 2) {
                v00 *= (2.0f / 3.0f); v01 *= (2.0f / 3.0f);
                v10 *= (2.0f / 3.0f); v11 *= (2.0f / 3.0f);
            }
            if (gc + 1 < N) {
                *(float2*)(Cm + (size_t)r0 * N + gc)       = make_float2(v00, v01);
                *(float2*)(Cm + (size_t)(r0 + 8) * N + gc) = make_float2(v10, v11);
            } else if (gc < N) {
                Cm[(size_t)r0 * N + gc]       = v00;
                Cm[(size_t)(r0 + 8) * N + gc] = v10;
            }
        }
    }
}

// ---------------------------------------------------------------------------
// Combined tf32 RN rounding pass over 4 segments (one launch)
// ---------------------------------------------------------------------------
__global__ void round_tf32_all(
    const float4* __restrict__ s0, float4* __restrict__ d0, int n0,
    const float4* __restrict__ s1, float4* __restrict__ d1, int n1,
    const float4* __restrict__ s2, float4* __restrict__ d2, int n2,
    const float4* __restrict__ s3, float4* __restrict__ d3, int n3)
{
    int i = blockIdx.x * blockDim.x + threadIdx.x;
    const float4* s; float4* d; int k;
    if (i < n0)                { s = s0; d = d0; k = i; }
    else if (i < n0 + n1)      { s = s1; d = d1; k = i - n0; }
    else if (i < n0 + n1 + n2) { s = s2; d = d2; k = i - n0 - n1; }
    else if (i < n0 + n1 + n2 + n3) { s = s3; d = d3; k = i - n0 - n1 - n2; }
    else return;
    float4 v = s[k];
    v.x = rtf32(v.x); v.y = rtf32(v.y); v.z = rtf32(v.z); v.w = rtf32(v.w);
    d[k] = v;
}

// ---------------------------------------------------------------------------
// pre[b,s,d] = f + std*nd + sum_r lrc*nlr   (stores tf32-rounded)
// ---------------------------------------------------------------------------
__global__ __launch_bounds__(256) void prelogits_kernel(
    const float* __restrict__ features, const float* __restrict__ lrc,
    const float* __restrict__ stdv, const float* __restrict__ nd,
    const float* __restrict__ nlr, float* __restrict__ pre)
{
    __shared__ float s_lrc[DD * 17];
    __shared__ float s_f[DD];
    __shared__ float s_std[DD];
    const int b = blockIdx.x, tid = threadIdx.x;

    const float* lb = lrc + (size_t)b * DD * RR;
    for (int i = tid; i < DD * RR; i += 256)
        s_lrc[(i >> 4) * 17 + (i & 15)] = lb[i];
    for (int i = tid; i < DD; i += 256) {
        s_f[i]   = features[(size_t)b * DD + i];
        s_std[i] = stdv[(size_t)b * DD + i];
    }
    __syncthreads();

    for (int s = 0; s < SS; s++) {
        const size_t row = (size_t)b * SS + s;
        const float* nlrp = nlr + row * RR;
        float nr[RR];
#pragma unroll
        for (int r = 0; r < RR; r++) nr[r] = nlrp[r];
        const float* ndp = nd + row * DD;
        float* pp = pre + row * DD;
#pragma unroll
        for (int dd = 0; dd < DD / 256; dd++) {
            const int d = tid + dd * 256;
            float a = fmaf(s_std[d], ndp[d], s_f[d]);
            const float* lp = &s_lrc[d * 17];
#pragma unroll
            for (int r = 0; r < RR; r++) a = fmaf(lp[r], nr[r], a);
            pp[d] = rtf32(a);
        }
    }
}

// ---------------------------------------------------------------------------
extern "C" void kernel_launch(void* const* d_in, const int* in_sizes, int n_in,
                              void* d_out, int out_size)
{
    const float* features   = (const float*)d_in[0];
    const float* W_cov      = (const float*)d_in[1];
    const float* b_cov      = (const float*)d_in[2];
    const float* W_diag     = (const float*)d_in[3];
    const float* b_diag     = (const float*)d_in[4];
    const float* W_cls      = (const float*)d_in[5];
    const float* b_cls      = (const float*)d_in[6];
    const float* noise_diag = (const float*)d_in[7];
    const float* noise_lr   = (const float*)d_in[8];
    float* out = (float*)d_out;

    float4 *lrc4, *std4, *pre4, *wcov4, *wcls4, *wdiag4, *feat4;
    cudaGetSymbolAddress((void**)&lrc4,   g_lrc4);
    cudaGetSymbolAddress((void**)&std4,   g_std4);
    cudaGetSymbolAddress((void**)&pre4,   g_pre4);
    cudaGetSymbolAddress((void**)&wcov4,  g_wcov4);
    cudaGetSymbolAddress((void**)&wcls4,  g_wcls4);
    cudaGetSymbolAddress((void**)&wdiag4, g_wdiag4);
    cudaGetSymbolAddress((void**)&feat4,  g_feat4);
    float* lrc  = (float*)lrc4;
    float* stdv = (float*)std4;
    float* pre  = (float*)pre4;

    cudaFuncSetAttribute(mma_gemm<0>, cudaFuncAttributeMaxDynamicSharedMemorySize, MMA_SMEM);
    cudaFuncSetAttribute(mma_gemm<1>, cudaFuncAttributeMaxDynamicSharedMemorySize, MMA_SMEM);
    cudaFuncSetAttribute(mma_gemm<2>, cudaFuncAttributeMaxDynamicSharedMemorySize, MMA_SMEM);

    // Pre-round tf32 inputs (RN), single fused launch
    const int n4_feat  = BB * DD / 4;
    const int n4_wcov  = DD * RR * DD / 4;
    const int n4_wcls  = CC * DD / 4;
    const int n4_wdiag = DD * DD / 4;
    const int n4_tot   = n4_feat + n4_wcov + n4_wcls + n4_wdiag;
    round_tf32_all<<<(n4_tot + 255) / 256, 256>>>(
        (const float4*)features, feat4,  n4_feat,
        (const float4*)W_cov,    wcov4,  n4_wcov,
        (const float4*)W_cls,    wcls4,  n4_wcls,
        (const float4*)W_diag,   wdiag4, n4_wdiag);

    // G1: lrc[B, D*R] = feat @ W_cov^T + b_cov
    mma_gemm<0><<<dim3((DD * RR) / 128, BB / 128), 256, MMA_SMEM>>>(
        (const float*)feat4, (const float*)wcov4, b_cov, lrc, BB, DD * RR, DD);

    // G2: std = softplus(feat @ W_diag^T + b_diag) + 1e-3
    mma_gemm<1><<<dim3(DD / 128, BB / 128), 256, MMA_SMEM>>>(
        (const float*)feat4, (const float*)wdiag4, b_diag, stdv, BB, DD, DD);

    // pre_logits (fused elementwise, tf32-rounded)
    prelogits_kernel<<<BB, 256>>>(features, lrc, stdv, noise_diag, noise_lr, pre);

    // G3: out = (pre @ W_cls^T + b_cls) / 1.5
    mma_gemm<2><<<dim3((CC + 127) / 128, (BB * SS) / 128), 256, MMA_SMEM>>>(
        pre, (const float*)wcls4, b_cls, out, BB * SS, CC, DD);
}

// round 9
// speedup vs baseline: 3.5497x; 1.0459x over previous
#include <cuda_runtime.h>
#include <math.h>
#include <stdint.h>

// Problem constants
#define BB 1024
#define SS 64
#define DD 512
#define RR 16
#define CC 1000

// ---------------------------------------------------------------------------
// Scratch (__device__ globals; float4 for 16B alignment needed by cp.async)
// ---------------------------------------------------------------------------
__device__ float4 g_lrc4  [(size_t)BB * DD * RR / 4];  // low_rank_cov [B, D*R]
__device__ float4 g_std4  [(size_t)BB * DD / 4];       // diagonal_std [B, D]
__device__ float4 g_pre4  [(size_t)BB * SS * DD / 4];  // pre_logits [B*S, D] (tf32-rounded)
__device__ float4 g_wcov4 [(size_t)DD * RR * DD / 4];  // tf32-rounded W_cov
__device__ float4 g_wcls4 [(size_t)CC * DD / 4];       // tf32-rounded W_cls
__device__ float4 g_wdiag4[(size_t)DD * DD / 4];       // tf32-rounded W_diag
__device__ float4 g_feat4 [(size_t)BB * DD / 4];       // tf32-rounded features

// ---------------------------------------------------------------------------
// Helpers
// ---------------------------------------------------------------------------
__device__ __forceinline__ uint32_t smem_u32(const void* p) {
    uint32_t a;
    asm("{ .reg .u64 t; cvta.to.shared.u64 t, %1; cvt.u32.u64 %0, t; }"
        : "=r"(a) : "l"(p));
    return a;
}
__device__ __forceinline__ float rtf32(float x) {  // round-to-nearest tf32
    uint32_t o; asm("cvt.rna.tf32.f32 %0, %1;" : "=r"(o) : "f"(x));
    return __uint_as_float(o);
}
__device__ __forceinline__ void cpa16(uint32_t dst, const void* src, uint32_t sz) {
    asm volatile("cp.async.cg.shared.global [%0], [%1], 16, %2;"
                 :: "r"(dst), "l"(src), "r"(sz) : "memory");
}
// m16n8k8 tf32 MMA (legacy HMMA path; legal on base sm_103 target)
__device__ __forceinline__ void mma8(float* d, const uint32_t* a, const uint32_t* b) {
    asm volatile(
        "mma.sync.aligned.m16n8k8.row.col.f32.tf32.tf32.f32 "
        "{%0,%1,%2,%3}, {%4,%5,%6,%7}, {%8,%9}, {%0,%1,%2,%3};"
        : "+f"(d[0]), "+f"(d[1]), "+f"(d[2]), "+f"(d[3])
        : "r"(a[0]), "r"(a[1]), "r"(a[2]), "r"(a[3]), "r"(b[0]), "r"(b[1]));
}
// ldmatrix x4 (b16 view; one m8n8.b16 tile == one 8x4 tf32 fragment tile)
__device__ __forceinline__ void ldsm4(uint32_t* r, uint32_t addr) {
    asm volatile("ldmatrix.sync.aligned.m8n8.x4.shared.b16 {%0,%1,%2,%3}, [%4];"
        : "=r"(r[0]), "=r"(r[1]), "=r"(r[2]), "=r"(r[3]) : "r"(addr));
}

// ---------------------------------------------------------------------------
// tf32 tensor-core GEMM: C[M,N] = A[M,K] @ B[N,K]^T + bias
// EPI: 0 plain, 1 softplus(x)+1e-3, 2 x*(2/3)
// 128x128 tile, K-slab 32, 3-stage cp.async (2 ahead), ONE barrier per slab,
// 8 warps (4m x 2n), warp 32x64, 2 CTAs/SM, ldmatrix fragment loads.
// ---------------------------------------------------------------------------
#define KSLAB 32
#define STGS  3
#define AHEAD 2
#define PAD   36
#define STAGE_FLOATS (2 * 128 * PAD)
#define BOFF  (128 * PAD)
#define MMA_SMEM (STGS * STAGE_FLOATS * 4 + 512)   // 111104 B -> 2 CTAs/SM

template <int EPI>
__global__ __launch_bounds__(256, 2) void mma_gemm(
    const float* __restrict__ A, const float* __restrict__ Bm,
    const float* __restrict__ bias, float* __restrict__ Cm,
    int M, int N, int K)
{
    extern __shared__ float sm[];
    float* s_bias = sm + STGS * STAGE_FLOATS;

    const int tid = threadIdx.x;
    const int bm  = blockIdx.y * 128;
    const int bn  = blockIdx.x * 128;

    if (tid < 128) s_bias[tid] = (bn + tid < N) ? bias[bn + tid] : 0.f;

    const int wid  = tid >> 5, lane = tid & 31;
    const int wm   = (wid & 3) * 32;
    const int wn   = (wid >> 2) * 64;
    const int g    = lane >> 2;
    const int t    = lane & 3;

    const uint32_t smb = smem_u32(sm);

    const int tile = lane >> 3, rit = lane & 7;
    uint32_t aoff[2], boff[4];
#pragma unroll
    for (int mt = 0; mt < 2; mt++)
        aoff[mt] = (uint32_t)(((wm + mt * 16 + ((tile & 1) << 3) + rit) * PAD
                               + ((tile >> 1) << 2)) * 4);
#pragma unroll
    for (int p = 0; p < 4; p++)
        boff[p] = (uint32_t)((BOFF + (wn + p * 16 + ((tile >> 1) << 3) + rit) * PAD
                               + ((tile & 1) << 2)) * 4);

    auto load_slab = [&](int s, int slab) {
        const int k0 = slab * KSLAB;
        const uint32_t abase = smb + (uint32_t)(s * STAGE_FLOATS) * 4u;
        const uint32_t bbase = abase + BOFF * 4u;
#pragma unroll
        for (int q = 0; q < 4; q++) {
            int idx = tid + q * 256;
            int m = idx >> 3, kc = idx & 7;
            cpa16(abase + (uint32_t)(m * PAD + kc * 4) * 4u,
                  A + (size_t)(bm + m) * K + k0 + kc * 4, 16);
        }
#pragma unroll
        for (int q = 0; q < 4; q++) {
            int idx = tid + q * 256;
            int n = idx >> 3, kc = idx & 7;
            int gn = bn + n;
            uint32_t sz = (gn < N) ? 16u : 0u;
            int gc = (gn < N) ? gn : (N - 1);
            cpa16(bbase + (uint32_t)(n * PAD + kc * 4) * 4u,
                  Bm + (size_t)gc * K + k0 + kc * 4, sz);
        }
    };

    float acc[2][8][4];
#pragma unroll
    for (int i = 0; i < 2; i++)
#pragma unroll
        for (int j = 0; j < 8; j++)
#pragma unroll
            for (int c = 0; c < 4; c++) acc[i][j][c] = 0.f;

    const int nslab = K / KSLAB;
    for (int p = 0; p < AHEAD; p++) {
        load_slab(p, p);
        asm volatile("cp.async.commit_group;" ::: "memory");
    }

    for (int j = 0; j < nslab; j++) {
        asm volatile("cp.async.wait_group 1;" ::: "memory");
        __syncthreads();
        if (j + AHEAD < nslab) load_slab((j + AHEAD) % STGS, j + AHEAD);
        asm volatile("cp.async.commit_group;" ::: "memory");

        const uint32_t stg = smb + (uint32_t)((j % STGS) * STAGE_FLOATS) * 4u;

#pragma unroll
        for (int ks = 0; ks < 4; ks++) {
            const uint32_t kb = stg + (uint32_t)ks * 32u;
            uint32_t af[2][4], bf[4][4];
            ldsm4(af[0], kb + aoff[0]);
            ldsm4(af[1], kb + aoff[1]);
#pragma unroll
            for (int p = 0; p < 4; p++) ldsm4(bf[p], kb + boff[p]);
#pragma unroll
            for (int mt = 0; mt < 2; mt++)
#pragma unroll
                for (int nt = 0; nt < 8; nt++)
                    mma8(acc[mt][nt], af[mt], &bf[nt >> 1][(nt & 1) << 1]);
        }
    }

#pragma unroll
    for (int mt = 0; mt < 2; mt++) {
        const int r0 = bm + wm + mt * 16 + g;
#pragma unroll
        for (int nt = 0; nt < 8; nt++) {
            const int lc = wn + nt * 8 + 2 * t;
            const int gc = bn + lc;
            float b0 = s_bias[lc], b1 = s_bias[lc + 1];
            float v00 = acc[mt][nt][0] + b0, v01 = acc[mt][nt][1] + b1;
            float v10 = acc[mt][nt][2] + b0, v11 = acc[mt][nt][3] + b1;
            if (EPI == 1) {
                v00 = fmaxf(v00, 0.f) + log1pf(expf(-fabsf(v00))) + 1e-3f;
                v01 = fmaxf(v01, 0.f) + log1pf(expf(-fabsf(v01))) + 1e-3f;
                v10 = fmaxf(v10, 0.f) + log1pf(expf(-fabsf(v10))) + 1e-3f;
                v11 = fmaxf(v11, 0.f) + log1pf(expf(-fabsf(v11))) + 1e-3f;
            } else if (EPI == 2) {
                v00 *= (2.0f / 3.0f); v01 *= (2.0f / 3.0f);
                v10 *= (2.0f / 3.0f); v11 *= (2.0f / 3.0f);
            }
            if (gc + 1 < N) {
                *(float2*)(Cm + (size_t)r0 * N + gc)       = make_float2(v00, v01);
                *(float2*)(Cm + (size_t)(r0 + 8) * N + gc) = make_float2(v10, v11);
            } else if (gc < N) {
                Cm[(size_t)r0 * N + gc]       = v00;
                Cm[(size_t)(r0 + 8) * N + gc] = v10;
            }
        }
    }
}

// ---------------------------------------------------------------------------
// Combined tf32 RN rounding pass over 4 segments (one launch)
// ---------------------------------------------------------------------------
__global__ void round_tf32_all(
    const float4* __restrict__ s0, float4* __restrict__ d0, int n0,
    const float4* __restrict__ s1, float4* __restrict__ d1, int n1,
    const float4* __restrict__ s2, float4* __restrict__ d2, int n2,
    const float4* __restrict__ s3, float4* __restrict__ d3, int n3)
{
    int i = blockIdx.x * blockDim.x + threadIdx.x;
    const float4* s; float4* d; int k;
    if (i < n0)                { s = s0; d = d0; k = i; }
    else if (i < n0 + n1)      { s = s1; d = d1; k = i - n0; }
    else if (i < n0 + n1 + n2) { s = s2; d = d2; k = i - n0 - n1; }
    else if (i < n0 + n1 + n2 + n3) { s = s3; d = d3; k = i - n0 - n1 - n2; }
    else return;
    float4 v = s[k];
    v.x = rtf32(v.x); v.y = rtf32(v.y); v.z = rtf32(v.z); v.w = rtf32(v.w);
    d[k] = v;
}

// ---------------------------------------------------------------------------
// pre[b,s,d] = f + std*nd + sum_r lrc*nlr   (tf32-rounded output)
// Register-resident lrc: thread owns 4 consecutive d, lrc[4][16] in regs.
// Grid = B blocks; 256 threads = 128 d-groups x 2 s-halves; 32 s-iters/thread.
// Zero LDS in hot loop; all gmem accesses float4.
// ---------------------------------------------------------------------------
__global__ __launch_bounds__(256, 2) void prelogits_kernel(
    const float* __restrict__ features, const float* __restrict__ lrc,
    const float* __restrict__ stdv, const float* __restrict__ nd,
    const float* __restrict__ nlr, float* __restrict__ pre)
{
    const int b   = blockIdx.x;
    const int tid = threadIdx.x;
    const int dg  = tid & 127;          // d-group: d0 = 4*dg
    const int sh  = tid >> 7;           // s-half: s in [32*sh, 32*sh+32)
    const int d0  = dg << 2;

    // lrc[b, d0..d0+3, 0..15] -> registers (row-major: d-major, r-contiguous)
    float lr[4][16];
    const float4* lp = (const float4*)(lrc + ((size_t)b * DD + d0) * RR);
#pragma unroll
    for (int i = 0; i < 4; i++)
#pragma unroll
        for (int q = 0; q < 4; q++) {
            float4 v = lp[i * 4 + q];
            lr[i][q * 4 + 0] = v.x; lr[i][q * 4 + 1] = v.y;
            lr[i][q * 4 + 2] = v.z; lr[i][q * 4 + 3] = v.w;
        }
    const float4 f4  = *(const float4*)(features + (size_t)b * DD + d0);
    const float4 sd4 = *(const float4*)(stdv     + (size_t)b * DD + d0);

    const size_t row0 = (size_t)b * SS + sh * 32;
#pragma unroll 4
    for (int si = 0; si < 32; si++) {
        const size_t row = row0 + si;
        float nr[16];
        const float4* np = (const float4*)(nlr + row * RR);
#pragma unroll
        for (int q = 0; q < 4; q++) {
            float4 v = np[q];   // broadcast across the 128 threads of this half
            nr[q * 4 + 0] = v.x; nr[q * 4 + 1] = v.y;
            nr[q * 4 + 2] = v.z; nr[q * 4 + 3] = v.w;
        }
        const float4 ndv = *(const float4*)(nd + row * DD + d0);
        float a0 = fmaf(sd4.x, ndv.x, f4.x);
        float a1 = fmaf(sd4.y, ndv.y, f4.y);
        float a2 = fmaf(sd4.z, ndv.z, f4.z);
        float a3 = fmaf(sd4.w, ndv.w, f4.w);
#pragma unroll
        for (int r = 0; r < 16; r++) {
            a0 = fmaf(lr[0][r], nr[r], a0);
            a1 = fmaf(lr[1][r], nr[r], a1);
            a2 = fmaf(lr[2][r], nr[r], a2);
            a3 = fmaf(lr[3][r], nr[r], a3);
        }
        *(float4*)(pre + row * DD + d0) =
            make_float4(rtf32(a0), rtf32(a1), rtf32(a2), rtf32(a3));
    }
}

// ---------------------------------------------------------------------------
extern "C" void kernel_launch(void* const* d_in, const int* in_sizes, int n_in,
                              void* d_out, int out_size)
{
    const float* features   = (const float*)d_in[0];
    const float* W_cov      = (const float*)d_in[1];
    const float* b_cov      = (const float*)d_in[2];
    const float* W_diag     = (const float*)d_in[3];
    const float* b_diag     = (const float*)d_in[4];
    const float* W_cls      = (const float*)d_in[5];
    const float* b_cls      = (const float*)d_in[6];
    const float* noise_diag = (const float*)d_in[7];
    const float* noise_lr   = (const float*)d_in[8];
    float* out = (float*)d_out;

    float4 *lrc4, *std4, *pre4, *wcov4, *wcls4, *wdiag4, *feat4;
    cudaGetSymbolAddress((void**)&lrc4,   g_lrc4);
    cudaGetSymbolAddress((void**)&std4,   g_std4);
    cudaGetSymbolAddress((void**)&pre4,   g_pre4);
    cudaGetSymbolAddress((void**)&wcov4,  g_wcov4);
    cudaGetSymbolAddress((void**)&wcls4,  g_wcls4);
    cudaGetSymbolAddress((void**)&wdiag4, g_wdiag4);
    cudaGetSymbolAddress((void**)&feat4,  g_feat4);
    float* lrc  = (float*)lrc4;
    float* stdv = (float*)std4;
    float* pre  = (float*)pre4;

    cudaFuncSetAttribute(mma_gemm<0>, cudaFuncAttributeMaxDynamicSharedMemorySize, MMA_SMEM);
    cudaFuncSetAttribute(mma_gemm<1>, cudaFuncAttributeMaxDynamicSharedMemorySize, MMA_SMEM);
    cudaFuncSetAttribute(mma_gemm<2>, cudaFuncAttributeMaxDynamicSharedMemorySize, MMA_SMEM);

    // Pre-round tf32 inputs (RN), single fused launch
    const int n4_feat  = BB * DD / 4;
    const int n4_wcov  = DD * RR * DD / 4;
    const int n4_wcls  = CC * DD / 4;
    const int n4_wdiag = DD * DD / 4;
    const int n4_tot   = n4_feat + n4_wcov + n4_wcls + n4_wdiag;
    round_tf32_all<<<(n4_tot + 255) / 256, 256>>>(
        (const float4*)features, feat4,  n4_feat,
        (const float4*)W_cov,    wcov4,  n4_wcov,
        (const float4*)W_cls,    wcls4,  n4_wcls,
        (const float4*)W_diag,   wdiag4, n4_wdiag);

    // G1: lrc[B, D*R] = feat @ W_cov^T + b_cov
    mma_gemm<0><<<dim3((DD * RR) / 128, BB / 128), 256, MMA_SMEM>>>(
        (const float*)feat4, (const float*)wcov4, b_cov, lrc, BB, DD * RR, DD);

    // G2: std = softplus(feat @ W_diag^T + b_diag) + 1e-3
    mma_gemm<1><<<dim3(DD / 128, BB / 128), 256, MMA_SMEM>>>(
        (const float*)feat4, (const float*)wdiag4, b_diag, stdv, BB, DD, DD);

    // pre_logits (register-resident lrc, fully vectorized)
    prelogits_kernel<<<BB, 256>>>(features, lrc, stdv, noise_diag, noise_lr, pre);

    // G3: out = (pre @ W_cls^T + b_cls) / 1.5
    mma_gemm<2><<<dim3((CC + 127) / 128, (BB * SS) / 128), 256, MMA_SMEM>>>(
        pre, (const float*)wcls4, b_cls, out, BB * SS, CC, DD);
}

// round 10
// speedup vs baseline: 3.6370x; 1.0246x over previous
#include <cuda_runtime.h>
#include <math.h>
#include <stdint.h>

// Problem constants
#define BB 1024
#define SS 64
#define DD 512
#define RR 16
#define CC 1000

// ---------------------------------------------------------------------------
// Scratch (__device__ globals; float4 for 16B alignment needed by cp.async)
// ---------------------------------------------------------------------------
__device__ float4 g_lrc4  [(size_t)BB * DD * RR / 4];  // low_rank_cov [B, D*R]
__device__ float4 g_std4  [(size_t)BB * DD / 4];       // diagonal_std [B, D]
__device__ float4 g_pre4  [(size_t)BB * SS * DD / 4];  // pre_logits [B*S, D] (tf32-rounded)
__device__ float4 g_wcov4 [(size_t)DD * RR * DD / 4];  // tf32-rounded W_cov
__device__ float4 g_wcls4 [(size_t)CC * DD / 4];       // tf32-rounded W_cls
__device__ float4 g_wdiag4[(size_t)DD * DD / 4];       // tf32-rounded W_diag
__device__ float4 g_feat4 [(size_t)BB * DD / 4];       // tf32-rounded features

// ---------------------------------------------------------------------------
// Helpers
// ---------------------------------------------------------------------------
__device__ __forceinline__ uint32_t smem_u32(const void* p) {
    uint32_t a;
    asm("{ .reg .u64 t; cvta.to.shared.u64 t, %1; cvt.u32.u64 %0, t; }"
        : "=r"(a) : "l"(p));
    return a;
}
__device__ __forceinline__ float rtf32(float x) {  // round-to-nearest tf32
    uint32_t o; asm("cvt.rna.tf32.f32 %0, %1;" : "=r"(o) : "f"(x));
    return __uint_as_float(o);
}
__device__ __forceinline__ void cpa16(uint32_t dst, const void* src, uint32_t sz) {
    asm volatile("cp.async.cg.shared.global [%0], [%1], 16, %2;"
                 :: "r"(dst), "l"(src), "r"(sz) : "memory");
}
// m16n8k8 tf32 MMA (legacy HMMA path; legal on base sm_103 target)
__device__ __forceinline__ void mma8(float* d, const uint32_t* a, const uint32_t* b) {
    asm volatile(
        "mma.sync.aligned.m16n8k8.row.col.f32.tf32.tf32.f32 "
        "{%0,%1,%2,%3}, {%4,%5,%6,%7}, {%8,%9}, {%0,%1,%2,%3};"
        : "+f"(d[0]), "+f"(d[1]), "+f"(d[2]), "+f"(d[3])
        : "r"(a[0]), "r"(a[1]), "r"(a[2]), "r"(a[3]), "r"(b[0]), "r"(b[1]));
}
// ldmatrix x4 (b16 view; one m8n8.b16 tile == one 8x4 tf32 fragment tile)
__device__ __forceinline__ void ldsm4(uint32_t* r, uint32_t addr) {
    asm volatile("ldmatrix.sync.aligned.m8n8.x4.shared.b16 {%0,%1,%2,%3}, [%4];"
        : "=r"(r[0]), "=r"(r[1]), "=r"(r[2]), "=r"(r[3]) : "r"(addr));
}

#define KSLAB 32
#define STGS  3
#define AHEAD 2
#define PAD   36
#define STAGE_FLOATS (2 * 128 * PAD)
#define BOFF  (128 * PAD)
#define MMA_SMEM (STGS * STAGE_FLOATS * 4 + 512)   // 111104 B -> 2 CTAs/SM

// ---------------------------------------------------------------------------
// G3 kernel: C = A @ B^T + bias, EPI = x*(2/3).  N=1000 needs guards.
// ---------------------------------------------------------------------------
__global__ __launch_bounds__(256, 2) void mma_gemm_g3(
    const float* __restrict__ A, const float* __restrict__ Bm,
    const float* __restrict__ bias, float* __restrict__ Cm,
    int M, int N, int K)
{
    extern __shared__ float sm[];
    float* s_bias = sm + STGS * STAGE_FLOATS;

    const int tid = threadIdx.x;
    const int bm  = blockIdx.y * 128;
    const int bn  = blockIdx.x * 128;

    if (tid < 128) s_bias[tid] = (bn + tid < N) ? bias[bn + tid] : 0.f;

    const int wid  = tid >> 5, lane = tid & 31;
    const int wm   = (wid & 3) * 32;
    const int wn   = (wid >> 2) * 64;
    const int g    = lane >> 2;
    const int t    = lane & 3;

    const uint32_t smb = smem_u32(sm);

    const int tile = lane >> 3, rit = lane & 7;
    uint32_t aoff[2], boff[4];
#pragma unroll
    for (int mt = 0; mt < 2; mt++)
        aoff[mt] = (uint32_t)(((wm + mt * 16 + ((tile & 1) << 3) + rit) * PAD
                               + ((tile >> 1) << 2)) * 4);
#pragma unroll
    for (int p = 0; p < 4; p++)
        boff[p] = (uint32_t)((BOFF + (wn + p * 16 + ((tile >> 1) << 3) + rit) * PAD
                               + ((tile & 1) << 2)) * 4);

    auto load_slab = [&](int s, int slab) {
        const int k0 = slab * KSLAB;
        const uint32_t abase = smb + (uint32_t)(s * STAGE_FLOATS) * 4u;
        const uint32_t bbase = abase + BOFF * 4u;
#pragma unroll
        for (int q = 0; q < 4; q++) {
            int idx = tid + q * 256;
            int m = idx >> 3, kc = idx & 7;
            cpa16(abase + (uint32_t)(m * PAD + kc * 4) * 4u,
                  A + (size_t)(bm + m) * K + k0 + kc * 4, 16);
        }
#pragma unroll
        for (int q = 0; q < 4; q++) {
            int idx = tid + q * 256;
            int n = idx >> 3, kc = idx & 7;
            int gn = bn + n;
            uint32_t sz = (gn < N) ? 16u : 0u;
            int gc = (gn < N) ? gn : (N - 1);
            cpa16(bbase + (uint32_t)(n * PAD + kc * 4) * 4u,
                  Bm + (size_t)gc * K + k0 + kc * 4, sz);
        }
    };

    float acc[2][8][4];
#pragma unroll
    for (int i = 0; i < 2; i++)
#pragma unroll
        for (int j = 0; j < 8; j++)
#pragma unroll
            for (int c = 0; c < 4; c++) acc[i][j][c] = 0.f;

    const int nslab = K / KSLAB;
    for (int p = 0; p < AHEAD; p++) {
        load_slab(p, p);
        asm volatile("cp.async.commit_group;" ::: "memory");
    }

    for (int j = 0; j < nslab; j++) {
        asm volatile("cp.async.wait_group 1;" ::: "memory");
        __syncthreads();
        if (j + AHEAD < nslab) load_slab((j + AHEAD) % STGS, j + AHEAD);
        asm volatile("cp.async.commit_group;" ::: "memory");

        const uint32_t stg = smb + (uint32_t)((j % STGS) * STAGE_FLOATS) * 4u;

#pragma unroll
        for (int ks = 0; ks < 4; ks++) {
            const uint32_t kb = stg + (uint32_t)ks * 32u;
            uint32_t af[2][4], bf[4][4];
            ldsm4(af[0], kb + aoff[0]);
            ldsm4(af[1], kb + aoff[1]);
#pragma unroll
            for (int p = 0; p < 4; p++) ldsm4(bf[p], kb + boff[p]);
#pragma unroll
            for (int mt = 0; mt < 2; mt++)
#pragma unroll
                for (int nt = 0; nt < 8; nt++)
                    mma8(acc[mt][nt], af[mt], &bf[nt >> 1][(nt & 1) << 1]);
        }
    }

#pragma unroll
    for (int mt = 0; mt < 2; mt++) {
        const int r0 = bm + wm + mt * 16 + g;
#pragma unroll
        for (int nt = 0; nt < 8; nt++) {
            const int lc = wn + nt * 8 + 2 * t;
            const int gc = bn + lc;
            float b0 = s_bias[lc], b1 = s_bias[lc + 1];
            float v00 = (acc[mt][nt][0] + b0) * (2.0f / 3.0f);
            float v01 = (acc[mt][nt][1] + b1) * (2.0f / 3.0f);
            float v10 = (acc[mt][nt][2] + b0) * (2.0f / 3.0f);
            float v11 = (acc[mt][nt][3] + b1) * (2.0f / 3.0f);
            if (gc + 1 < N) {
                *(float2*)(Cm + (size_t)r0 * N + gc)       = make_float2(v00, v01);
                *(float2*)(Cm + (size_t)(r0 + 8) * N + gc) = make_float2(v10, v11);
            } else if (gc < N) {
                Cm[(size_t)r0 * N + gc]       = v00;
                Cm[(size_t)(r0 + 8) * N + gc] = v10;
            }
        }
    }
}

// ---------------------------------------------------------------------------
// Dual GEMM (G1 + G2 in one launch): blocks x<NB1 -> lrc (plain epi),
// blocks x>=NB1 -> stdv (softplus epi). All N multiples of 128 (no guards).
// ---------------------------------------------------------------------------
#define NB1 64    // (DD*RR)/128 n-blocks for G1; G2 adds DD/128 = 4

__global__ __launch_bounds__(256, 2) void mma_gemm_dual(
    const float* __restrict__ A,
    const float* __restrict__ B1, const float* __restrict__ bias1,
    float* __restrict__ C1,
    const float* __restrict__ B2, const float* __restrict__ bias2,
    float* __restrict__ C2,
    int M, int K)
{
    extern __shared__ float sm[];
    float* s_bias = sm + STGS * STAGE_FLOATS;

    const int tid = threadIdx.x;
    const int bm  = blockIdx.y * 128;
    const bool g2 = (blockIdx.x >= NB1);
    const int bn  = (g2 ? (blockIdx.x - NB1) : blockIdx.x) * 128;
    const float* Bm   = g2 ? B2 : B1;
    const float* bias = g2 ? bias2 : bias1;
    float* Cm         = g2 ? C2 : C1;
    const int N       = g2 ? DD : DD * RR;

    if (tid < 128) s_bias[tid] = bias[bn + tid];

    const int wid  = tid >> 5, lane = tid & 31;
    const int wm   = (wid & 3) * 32;
    const int wn   = (wid >> 2) * 64;
    const int g    = lane >> 2;
    const int t    = lane & 3;

    const uint32_t smb = smem_u32(sm);

    const int tile = lane >> 3, rit = lane & 7;
    uint32_t aoff[2], boff[4];
#pragma unroll
    for (int mt = 0; mt < 2; mt++)
        aoff[mt] = (uint32_t)(((wm + mt * 16 + ((tile & 1) << 3) + rit) * PAD
                               + ((tile >> 1) << 2)) * 4);
#pragma unroll
    for (int p = 0; p < 4; p++)
        boff[p] = (uint32_t)((BOFF + (wn + p * 16 + ((tile >> 1) << 3) + rit) * PAD
                               + ((tile & 1) << 2)) * 4);

    auto load_slab = [&](int s, int slab) {
        const int k0 = slab * KSLAB;
        const uint32_t abase = smb + (uint32_t)(s * STAGE_FLOATS) * 4u;
        const uint32_t bbase = abase + BOFF * 4u;
#pragma unroll
        for (int q = 0; q < 4; q++) {
            int idx = tid + q * 256;
            int m = idx >> 3, kc = idx & 7;
            cpa16(abase + (uint32_t)(m * PAD + kc * 4) * 4u,
                  A + (size_t)(bm + m) * K + k0 + kc * 4, 16);
        }
#pragma unroll
        for (int q = 0; q < 4; q++) {
            int idx = tid + q * 256;
            int n = idx >> 3, kc = idx & 7;
            cpa16(bbase + (uint32_t)(n * PAD + kc * 4) * 4u,
                  Bm + (size_t)(bn + n) * K + k0 + kc * 4, 16);
        }
    };

    float acc[2][8][4];
#pragma unroll
    for (int i = 0; i < 2; i++)
#pragma unroll
        for (int j = 0; j < 8; j++)
#pragma unroll
            for (int c = 0; c < 4; c++) acc[i][j][c] = 0.f;

    const int nslab = K / KSLAB;
    for (int p = 0; p < AHEAD; p++) {
        load_slab(p, p);
        asm volatile("cp.async.commit_group;" ::: "memory");
    }

    for (int j = 0; j < nslab; j++) {
        asm volatile("cp.async.wait_group 1;" ::: "memory");
        __syncthreads();
        if (j + AHEAD < nslab) load_slab((j + AHEAD) % STGS, j + AHEAD);
        asm volatile("cp.async.commit_group;" ::: "memory");

        const uint32_t stg = smb + (uint32_t)((j % STGS) * STAGE_FLOATS) * 4u;

#pragma unroll
        for (int ks = 0; ks < 4; ks++) {
            const uint32_t kb = stg + (uint32_t)ks * 32u;
            uint32_t af[2][4], bf[4][4];
            ldsm4(af[0], kb + aoff[0]);
            ldsm4(af[1], kb + aoff[1]);
#pragma unroll
            for (int p = 0; p < 4; p++) ldsm4(bf[p], kb + boff[p]);
#pragma unroll
            for (int mt = 0; mt < 2; mt++)
#pragma unroll
                for (int nt = 0; nt < 8; nt++)
                    mma8(acc[mt][nt], af[mt], &bf[nt >> 1][(nt & 1) << 1]);
        }
    }

#pragma unroll
    for (int mt = 0; mt < 2; mt++) {
        const int r0 = bm + wm + mt * 16 + g;
#pragma unroll
        for (int nt = 0; nt < 8; nt++) {
            const int lc = wn + nt * 8 + 2 * t;
            const int gc = bn + lc;
            float b0 = s_bias[lc], b1 = s_bias[lc + 1];
            float v00 = acc[mt][nt][0] + b0, v01 = acc[mt][nt][1] + b1;
            float v10 = acc[mt][nt][2] + b0, v11 = acc[mt][nt][3] + b1;
            if (g2) {   // uniform branch per block
                v00 = fmaxf(v00, 0.f) + log1pf(expf(-fabsf(v00))) + 1e-3f;
                v01 = fmaxf(v01, 0.f) + log1pf(expf(-fabsf(v01))) + 1e-3f;
                v10 = fmaxf(v10, 0.f) + log1pf(expf(-fabsf(v10))) + 1e-3f;
                v11 = fmaxf(v11, 0.f) + log1pf(expf(-fabsf(v11))) + 1e-3f;
            }
            *(float2*)(Cm + (size_t)r0 * N + gc)       = make_float2(v00, v01);
            *(float2*)(Cm + (size_t)(r0 + 8) * N + gc) = make_float2(v10, v11);
        }
    }
}

// ---------------------------------------------------------------------------
// Combined tf32 RN rounding pass over 4 segments (one launch)
// ---------------------------------------------------------------------------
__global__ void round_tf32_all(
    const float4* __restrict__ s0, float4* __restrict__ d0, int n0,
    const float4* __restrict__ s1, float4* __restrict__ d1, int n1,
    const float4* __restrict__ s2, float4* __restrict__ d2, int n2,
    const float4* __restrict__ s3, float4* __restrict__ d3, int n3)
{
    int i = blockIdx.x * blockDim.x + threadIdx.x;
    const float4* s; float4* d; int k;
    if (i < n0)                { s = s0; d = d0; k = i; }
    else if (i < n0 + n1)      { s = s1; d = d1; k = i - n0; }
    else if (i < n0 + n1 + n2) { s = s2; d = d2; k = i - n0 - n1; }
    else if (i < n0 + n1 + n2 + n3) { s = s3; d = d3; k = i - n0 - n1 - n2; }
    else return;
    float4 v = s[k];
    v.x = rtf32(v.x); v.y = rtf32(v.y); v.z = rtf32(v.z); v.w = rtf32(v.w);
    d[k] = v;
}

// ---------------------------------------------------------------------------
// pre[b,s,d] = f + std*nd + sum_r lrc*nlr   (tf32-rounded output)
// v3: thread owns 2 d (lr[2][16] = 32 regs), grid BB x 2 s-halves,
// 3 CTAs/SM, 32 s-iters/thread, float2/float4 vectorized, zero LDS.
// ---------------------------------------------------------------------------
__global__ __launch_bounds__(256, 3) void prelogits_kernel(
    const float* __restrict__ features, const float* __restrict__ lrc,
    const float* __restrict__ stdv, const float* __restrict__ nd,
    const float* __restrict__ nlr, float* __restrict__ pre)
{
    const int b   = blockIdx.x >> 1;
    const int sh  = blockIdx.x & 1;
    const int tid = threadIdx.x;        // d-group: d0 = 2*tid, covers D=512
    const int d0  = tid << 1;

    float lr[2][16];
    const float4* lp = (const float4*)(lrc + ((size_t)b * DD + d0) * RR);
#pragma unroll
    for (int i = 0; i < 2; i++)
#pragma unroll
        for (int q = 0; q < 4; q++) {
            float4 v = lp[i * 4 + q];
            lr[i][q * 4 + 0] = v.x; lr[i][q * 4 + 1] = v.y;
            lr[i][q * 4 + 2] = v.z; lr[i][q * 4 + 3] = v.w;
        }
    const float2 f2  = *(const float2*)(features + (size_t)b * DD + d0);
    const float2 sd2 = *(const float2*)(stdv     + (size_t)b * DD + d0);

    const size_t row0 = (size_t)b * SS + sh * 32;
#pragma unroll 4
    for (int si = 0; si < 32; si++) {
        const size_t row = row0 + si;
        float nr[16];
        const float4* np = (const float4*)(nlr + row * RR);
#pragma unroll
        for (int q = 0; q < 4; q++) {
            float4 v = np[q];   // uniform across block -> warp broadcast
            nr[q * 4 + 0] = v.x; nr[q * 4 + 1] = v.y;
            nr[q * 4 + 2] = v.z; nr[q * 4 + 3] = v.w;
        }
        const float2 ndv = *(const float2*)(nd + row * DD + d0);
        float a0 = fmaf(sd2.x, ndv.x, f2.x);
        float a1 = fmaf(sd2.y, ndv.y, f2.y);
#pragma unroll
        for (int r = 0; r < 16; r++) {
            a0 = fmaf(lr[0][r], nr[r], a0);
            a1 = fmaf(lr[1][r], nr[r], a1);
        }
        *(float2*)(pre + row * DD + d0) = make_float2(rtf32(a0), rtf32(a1));
    }
}

// ---------------------------------------------------------------------------
extern "C" void kernel_launch(void* const* d_in, const int* in_sizes, int n_in,
                              void* d_out, int out_size)
{
    const float* features   = (const float*)d_in[0];
    const float* W_cov      = (const float*)d_in[1];
    const float* b_cov      = (const float*)d_in[2];
    const float* W_diag     = (const float*)d_in[3];
    const float* b_diag     = (const float*)d_in[4];
    const float* W_cls      = (const float*)d_in[5];
    const float* b_cls      = (const float*)d_in[6];
    const float* noise_diag = (const float*)d_in[7];
    const float* noise_lr   = (const float*)d_in[8];
    float* out = (float*)d_out;

    float4 *lrc4, *std4, *pre4, *wcov4, *wcls4, *wdiag4, *feat4;
    cudaGetSymbolAddress((void**)&lrc4,   g_lrc4);
    cudaGetSymbolAddress((void**)&std4,   g_std4);
    cudaGetSymbolAddress((void**)&pre4,   g_pre4);
    cudaGetSymbolAddress((void**)&wcov4,  g_wcov4);
    cudaGetSymbolAddress((void**)&wcls4,  g_wcls4);
    cudaGetSymbolAddress((void**)&wdiag4, g_wdiag4);
    cudaGetSymbolAddress((void**)&feat4,  g_feat4);
    float* lrc  = (float*)lrc4;
    float* stdv = (float*)std4;
    float* pre  = (float*)pre4;

    cudaFuncSetAttribute(mma_gemm_g3,   cudaFuncAttributeMaxDynamicSharedMemorySize, MMA_SMEM);
    cudaFuncSetAttribute(mma_gemm_dual, cudaFuncAttributeMaxDynamicSharedMemorySize, MMA_SMEM);

    // Pre-round tf32 inputs (RN), single fused launch
    const int n4_feat  = BB * DD / 4;
    const int n4_wcov  = DD * RR * DD / 4;
    const int n4_wcls  = CC * DD / 4;
    const int n4_wdiag = DD * DD / 4;
    const int n4_tot   = n4_feat + n4_wcov + n4_wcls + n4_wdiag;
    round_tf32_all<<<(n4_tot + 255) / 256, 256>>>(
        (const float4*)features, feat4,  n4_feat,
        (const float4*)W_cov,    wcov4,  n4_wcov,
        (const float4*)W_cls,    wcls4,  n4_wcls,
        (const float4*)W_diag,   wdiag4, n4_wdiag);

    // G1+G2 fused: lrc = feat @ W_cov^T + b_cov ; std = softplus(feat @ W_diag^T + b_diag)+1e-3
    mma_gemm_dual<<<dim3(NB1 + DD / 128, BB / 128), 256, MMA_SMEM>>>(
        (const float*)feat4,
        (const float*)wcov4,  b_cov,  lrc,
        (const float*)wdiag4, b_diag, stdv,
        BB, DD);

    // pre_logits (2-d-per-thread, 3 CTAs/SM)
    prelogits_kernel<<<BB * 2, 256>>>(features, lrc, stdv, noise_diag, noise_lr, pre);

    // G3: out = (pre @ W_cls^T + b_cls) / 1.5
    mma_gemm_g3<<<dim3((CC + 127) / 128, (BB * SS) / 128), 256, MMA_SMEM>>>(
        pre, (const float*)wcls4, b_cls, out, BB * SS, CC, DD);
}